// round 10
// baseline (speedup 1.0000x reference)
#include <cuda_runtime.h>
#include <cuda_bf16.h>
#include <mma.h>
#include <math.h>
#include <stdint.h>

using namespace nvcuda;

// Problem constants
#define BB 2
#define SS 2048
#define DD 1024
#define HH 16
#define HD 64
#define MROWS (BB*SS)   // 4096
#define NELEM (BB*SS*DD)   // 4M
#define WELEM (DD*DD)      // 1M

// ---------------------------------------------------------------------------
// Global scratch (allocation-free rule: __device__ globals), all bf16 hi/lo
// ---------------------------------------------------------------------------
__device__ __nv_bfloat16 g_iqh[NELEM], g_iql[NELEM];   // split(queries)
__device__ __nv_bfloat16 g_ikh[NELEM], g_ikl[NELEM];   // split(keys)
__device__ __nv_bfloat16 g_ivh[NELEM], g_ivl[NELEM];   // split(values)
__device__ __nv_bfloat16 g_wqh[WELEM], g_wql[WELEM];
__device__ __nv_bfloat16 g_wkh[WELEM], g_wkl[WELEM];
__device__ __nv_bfloat16 g_wvh[WELEM], g_wvl[WELEM];
__device__ __nv_bfloat16 g_woh[WELEM], g_wol[WELEM];
__device__ __nv_bfloat16 g_Qh[NELEM], g_Ql[NELEM];     // projected Q hi/lo
__device__ __nv_bfloat16 g_Kh[NELEM], g_Kl[NELEM];
__device__ __nv_bfloat16 g_Vh[NELEM], g_Vl[NELEM];
__device__ __nv_bfloat16 g_Ch[NELEM], g_Cl[NELEM];     // attention ctx hi/lo

// Split float4 -> packed hi (4 bf16) + lo (4 bf16).
__device__ __forceinline__ void bsplit4(float4 v, uint2& h, uint2& l) {
    __nv_bfloat162 h0, h1, l0, l1;
    h0.x = __float2bfloat16(v.x); h0.y = __float2bfloat16(v.y);
    h1.x = __float2bfloat16(v.z); h1.y = __float2bfloat16(v.w);
    l0.x = __float2bfloat16(v.x - __bfloat162float(h0.x));
    l0.y = __float2bfloat16(v.y - __bfloat162float(h0.y));
    l1.x = __float2bfloat16(v.z - __bfloat162float(h1.x));
    l1.y = __float2bfloat16(v.w - __bfloat162float(h1.y));
    h.x = *(uint32_t*)&h0; h.y = *(uint32_t*)&h1;
    l.x = *(uint32_t*)&l0; l.y = *(uint32_t*)&l1;
}

// Pack two floats -> bf16x2 hi + bf16x2 lo.
__device__ __forceinline__ void split2(float x, float y, uint32_t& hi, uint32_t& lo) {
    uint32_t h;
    asm("cvt.rn.bf16x2.f32 %0, %1, %2;" : "=r"(h) : "f"(y), "f"(x));
    float hx = __uint_as_float(h << 16);
    float hy = __uint_as_float(h & 0xffff0000u);
    uint32_t l;
    asm("cvt.rn.bf16x2.f32 %0, %1, %2;" : "=r"(l) : "f"(y - hy), "f"(x - hx));
    hi = h; lo = l;
}

__device__ __forceinline__ uint32_t smem_u32(const void* p) {
    uint32_t a;
    asm("{ .reg .u64 t; cvta.to.shared.u64 t, %1; cvt.u32.u64 %0, t; }"
        : "=r"(a) : "l"(p));
    return a;
}

__device__ __forceinline__ void cp16(uint32_t dst, const void* src) {
    asm volatile("cp.async.cg.shared.global [%0], [%1], 16;" :: "r"(dst), "l"(src));
}

__device__ __forceinline__ void ldsm_x4(uint32_t* r, uint32_t addr) {
    asm volatile("ldmatrix.sync.aligned.m8n8.x4.shared.b16 {%0,%1,%2,%3}, [%4];"
        : "=r"(r[0]), "=r"(r[1]), "=r"(r[2]), "=r"(r[3]) : "r"(addr));
}
__device__ __forceinline__ void ldsm_x4_t(uint32_t* r, uint32_t addr) {
    asm volatile("ldmatrix.sync.aligned.m8n8.x4.trans.shared.b16 {%0,%1,%2,%3}, [%4];"
        : "=r"(r[0]), "=r"(r[1]), "=r"(r[2]), "=r"(r[3]) : "r"(addr));
}
__device__ __forceinline__ void mma16816(float* c, const uint32_t* a, uint32_t b0, uint32_t b1) {
    asm volatile(
        "mma.sync.aligned.m16n8k16.row.col.f32.bf16.bf16.f32 "
        "{%0,%1,%2,%3}, {%4,%5,%6,%7}, {%8,%9}, {%0,%1,%2,%3};"
        : "+f"(c[0]), "+f"(c[1]), "+f"(c[2]), "+f"(c[3])
        : "r"(a[0]), "r"(a[1]), "r"(a[2]), "r"(a[3]), "r"(b0), "r"(b1));
}

// ===========================================================================
// Split kernel: fp32 -> bf16 hi/lo, vectorized.
// ===========================================================================
__global__ __launch_bounds__(256) void split_k(
    const float* __restrict__ x, __nv_bfloat16* __restrict__ h,
    __nv_bfloat16* __restrict__ l, int n4)
{
    int i = blockIdx.x * blockDim.x + threadIdx.x;
    if (i < n4) {
        float4 v = ((const float4*)x)[i];
        uint2 hh, ll;
        bsplit4(v, hh, ll);
        ((uint2*)h)[i] = hh;
        ((uint2*)l)[i] = ll;
    }
}

// ===========================================================================
// bf16-in tensor GEMM, cp.async double-buffered. C = alpha * A @ B.
// A,B given as pre-split hi/lo bf16 (row-major, K-stride = N-stride = 1024).
// out_bf16: 0 -> fp32 C; 1 -> split C into (Ch, Cl) bf16.
// 128x128 tile, BK=32, 256 threads = 8 warps (4x2), warp tile 32x64.
// ===========================================================================
#define BK 32
#define NC (DD / BK)       // 32
#define LDAs 40
#define LDBs 136
#define STG_A (128 * LDAs)          // elems
#define STG_B (BK * LDBs)
#define OFF_AL (STG_A * 2)          // bytes
#define OFF_BH (2 * STG_A * 2)
#define OFF_BL (2 * STG_A * 2 + STG_B * 2)
#define STG_BYTES ((2 * STG_A + 2 * STG_B) * 2)   // 37888
#define GEMM_SMEM (2 * STG_BYTES)                  // 75776

__device__ __forceinline__ void issue_stage(
    uint32_t st, const __nv_bfloat16* __restrict__ Ahg,
    const __nv_bfloat16* __restrict__ Alg,
    const __nv_bfloat16* __restrict__ Bhg,
    const __nv_bfloat16* __restrict__ Blg,
    int brow, int bcol, int k0, int tid)
{
    // A: 128x32, tid<128 -> hi, else lo; one row (4x16B) per thread
    {
        const __nv_bfloat16* Ag = (tid < 128) ? Ahg : Alg;
        uint32_t dst = st + ((tid < 128) ? 0u : (uint32_t)OFF_AL)
                     + (uint32_t)(tid & 127) * (LDAs * 2);
        const __nv_bfloat16* src = Ag + (size_t)(brow + (tid & 127)) * DD + k0;
        #pragma unroll
        for (int j = 0; j < 4; j++)
            cp16(dst + j * 16, src + j * 8);
    }
    // B: 32x128 hi + lo = 1024 x 16B chunks; 4 per thread
    #pragma unroll
    for (int j = 0; j < 4; j++) {
        int c  = tid + 256 * j;
        int c2 = c & 511;
        int kr = c2 >> 4;
        int cc = c2 & 15;
        const __nv_bfloat16* Bg = (c < 512) ? Bhg : Blg;
        uint32_t dst = st + ((c < 512) ? (uint32_t)OFF_BH : (uint32_t)OFF_BL)
                     + (uint32_t)kr * (LDBs * 2) + (uint32_t)cc * 16;
        cp16(dst, Bg + (size_t)(k0 + kr) * DD + bcol + cc * 8);
    }
}

__global__ __launch_bounds__(256) void gemm_bf16(
    const __nv_bfloat16* __restrict__ Ahg, const __nv_bfloat16* __restrict__ Alg,
    const __nv_bfloat16* __restrict__ Bhg, const __nv_bfloat16* __restrict__ Blg,
    float* __restrict__ Cf, __nv_bfloat16* __restrict__ Chg, __nv_bfloat16* __restrict__ Clg,
    float alpha, int out_bf16)
{
    extern __shared__ char smraw[];
    const uint32_t sb = smem_u32(smraw);
    const int tid  = threadIdx.x;
    const int wid  = tid >> 5;
    const int lane = tid & 31;
    const int wm   = wid & 3;
    const int wn   = wid >> 2;
    const int brow = blockIdx.y * 128;
    const int bcol = blockIdx.x * 128;

    wmma::fragment<wmma::accumulator, 16, 16, 16, float> acc[2][4];
    #pragma unroll
    for (int i = 0; i < 2; i++)
        #pragma unroll
        for (int j = 0; j < 4; j++)
            wmma::fill_fragment(acc[i][j], 0.0f);

    issue_stage(sb, Ahg, Alg, Bhg, Blg, brow, bcol, 0, tid);
    asm volatile("cp.async.commit_group;" ::: "memory");

    for (int c = 0; c < NC; c++) {
        const int st = c & 1;
        if (c + 1 < NC) {
            issue_stage(sb + (st ^ 1) * STG_BYTES, Ahg, Alg, Bhg, Blg,
                        brow, bcol, (c + 1) * BK, tid);
            asm volatile("cp.async.commit_group;" ::: "memory");
            asm volatile("cp.async.wait_group 1;" ::: "memory");
        } else {
            asm volatile("cp.async.wait_group 0;" ::: "memory");
        }
        __syncthreads();

        const __nv_bfloat16* Ah = (const __nv_bfloat16*)(smraw + st * STG_BYTES);
        const __nv_bfloat16* Al = Ah + STG_A;
        const __nv_bfloat16* Bh = Al + STG_A;
        const __nv_bfloat16* Bl = Bh + STG_B;

        #pragma unroll
        for (int ks = 0; ks < 2; ks++) {
            wmma::fragment<wmma::matrix_a, 16, 16, 16, __nv_bfloat16, wmma::row_major> ah[2], al[2];
            wmma::fragment<wmma::matrix_b, 16, 16, 16, __nv_bfloat16, wmma::row_major> bh[4], bl[4];
            #pragma unroll
            for (int i = 0; i < 2; i++) {
                wmma::load_matrix_sync(ah[i], Ah + (wm * 32 + i * 16) * LDAs + ks * 16, LDAs);
                wmma::load_matrix_sync(al[i], Al + (wm * 32 + i * 16) * LDAs + ks * 16, LDAs);
            }
            #pragma unroll
            for (int j = 0; j < 4; j++) {
                wmma::load_matrix_sync(bh[j], Bh + (ks * 16) * LDBs + wn * 64 + j * 16, LDBs);
                wmma::load_matrix_sync(bl[j], Bl + (ks * 16) * LDBs + wn * 64 + j * 16, LDBs);
            }
            #pragma unroll
            for (int i = 0; i < 2; i++)
                #pragma unroll
                for (int j = 0; j < 4; j++) {
                    wmma::mma_sync(acc[i][j], ah[i], bh[j], acc[i][j]);
                    wmma::mma_sync(acc[i][j], ah[i], bl[j], acc[i][j]);
                    wmma::mma_sync(acc[i][j], al[i], bh[j], acc[i][j]);
                }
        }
        __syncthreads();
    }

    // scale
    #pragma unroll
    for (int i = 0; i < 2; i++)
        #pragma unroll
        for (int j = 0; j < 4; j++)
            #pragma unroll
            for (int e = 0; e < acc[i][j].num_elements; e++)
                acc[i][j].x[e] *= alpha;

    if (!out_bf16) {
        #pragma unroll
        for (int i = 0; i < 2; i++)
            #pragma unroll
            for (int j = 0; j < 4; j++) {
                float* Cp = Cf + (size_t)(brow + wm * 32 + i * 16) * DD + bcol + wn * 64 + j * 16;
                wmma::store_matrix_sync(Cp, acc[i][j], DD, wmma::mem_row_major);
            }
    } else {
        // stage warp patch (32x64 fp32 = 8KB) in smem, then split elementwise
        float* ws = (float*)(smraw) + wid * 2048;
        #pragma unroll
        for (int i = 0; i < 2; i++)
            #pragma unroll
            for (int j = 0; j < 4; j++)
                wmma::store_matrix_sync(ws + i * 16 * 64 + j * 16, acc[i][j], 64, wmma::mem_row_major);
        __syncwarp();
        const float* src = ws + lane * 64;
        int grow = brow + wm * 32 + lane;
        __nv_bfloat16* chp = Chg + (size_t)grow * DD + bcol + wn * 64;
        __nv_bfloat16* clp = Clg + (size_t)grow * DD + bcol + wn * 64;
        #pragma unroll
        for (int g = 0; g < 8; g++) {
            uint4 hv, lv;
            split2(src[8 * g + 0], src[8 * g + 1], hv.x, lv.x);
            split2(src[8 * g + 2], src[8 * g + 3], hv.y, lv.y);
            split2(src[8 * g + 4], src[8 * g + 5], hv.z, lv.z);
            split2(src[8 * g + 6], src[8 * g + 7], hv.w, lv.w);
            *(uint4*)(chp + 8 * g) = hv;
            *(uint4*)(clp + 8 * g) = lv;
        }
    }
}

// ===========================================================================
// Raw-mma flash attention, bf16 hi/lo inputs, bf16 hi/lo ctx output.
// ===========================================================================
#define LQ  72
#define LSO 72

__global__ __launch_bounds__(256, 2) void attn_mma(
    const __nv_bfloat16* __restrict__ Qhg, const __nv_bfloat16* __restrict__ Qlg,
    const __nv_bfloat16* __restrict__ Khg, const __nv_bfloat16* __restrict__ Klg,
    const __nv_bfloat16* __restrict__ Vhg, const __nv_bfloat16* __restrict__ Vlg,
    __nv_bfloat16* __restrict__ Chg, __nv_bfloat16* __restrict__ Clg)
{
    __shared__ __nv_bfloat16 KVs[4 * 64 * LQ];
    __shared__ float lbuf[2][64];

    const int tid  = threadIdx.x;
    const int lane = tid & 31;
    const int wid  = tid >> 5;
    const int rm   = wid >> 1;
    const int cn   = wid & 1;
    const int q0   = blockIdx.x * 64;
    const int h    = blockIdx.y;
    const int b    = blockIdx.z;
    const int row  = tid >> 2;
    const int cseg = (tid & 3) * 16;
    const size_t hoff = (size_t)h * HD;
    const size_t gbase = ((size_t)(b * SS) + q0 + row) * DD + hoff + cseg;

    __nv_bfloat16* Kh = KVs;
    __nv_bfloat16* Kl = KVs + 64 * LQ;
    __nv_bfloat16* Vh = KVs + 2 * 64 * LQ;
    __nv_bfloat16* Vl = KVs + 3 * 64 * LQ;

    const uint32_t base = smem_u32(KVs);
    const int rA = lane & 15, cA = (lane >> 4) * 8;
    const int rK = (lane & 7) + ((lane & 16) >> 1), cK = lane & 8;

    // ---- stage Q (hi->Vh, lo->Vl), hoist A-fragments --------------------
    {
        int bi = row * LQ + cseg;
        *(uint4*)&Vh[bi]     = *(const uint4*)(Qhg + gbase);
        *(uint4*)&Vh[bi + 8] = *(const uint4*)(Qhg + gbase + 8);
        *(uint4*)&Vl[bi]     = *(const uint4*)(Qlg + gbase);
        *(uint4*)&Vl[bi + 8] = *(const uint4*)(Qlg + gbase + 8);
    }
    __syncthreads();

    uint32_t qh[4][4], ql[4][4];
    #pragma unroll
    for (int d = 0; d < 4; d++) {
        uint32_t a = base + (uint32_t)(2 * 64 * LQ + (rm * 16 + rA) * LQ + d * 16 + cA) * 2;
        ldsm_x4(qh[d], a);
        ldsm_x4(ql[d], a + 64 * LQ * 2);
    }

    float oacc[8][4];
    #pragma unroll
    for (int n = 0; n < 8; n++)
        #pragma unroll
        for (int e = 0; e < 4; e++) oacc[n][e] = 0.0f;
    float ls0 = 0.0f, ls1 = 0.0f;

    for (int kv0 = 0; kv0 < SS; kv0 += 64) {
        __syncthreads();

        // ---- load K,V hi/lo tiles directly (pre-split) ----------------
        {
            const size_t kb = ((size_t)(b * SS) + kv0 + row) * DD + hoff + cseg;
            int bi = row * LQ + cseg;
            *(uint4*)&Kh[bi]     = *(const uint4*)(Khg + kb);
            *(uint4*)&Kh[bi + 8] = *(const uint4*)(Khg + kb + 8);
            *(uint4*)&Kl[bi]     = *(const uint4*)(Klg + kb);
            *(uint4*)&Kl[bi + 8] = *(const uint4*)(Klg + kb + 8);
            *(uint4*)&Vh[bi]     = *(const uint4*)(Vhg + kb);
            *(uint4*)&Vh[bi + 8] = *(const uint4*)(Vhg + kb + 8);
            *(uint4*)&Vl[bi]     = *(const uint4*)(Vlg + kb);
            *(uint4*)&Vl[bi + 8] = *(const uint4*)(Vlg + kb + 8);
        }
        __syncthreads();

        // ---- S = Q @ K^T (3-term) --------------------------------------
        float s[4][4];
        #pragma unroll
        for (int j = 0; j < 4; j++)
            #pragma unroll
            for (int e = 0; e < 4; e++) s[j][e] = 0.0f;

        #pragma unroll
        for (int d = 0; d < 4; d++) {
            #pragma unroll
            for (int jp = 0; jp < 2; jp++) {
                uint32_t kh[4], kl[4];
                uint32_t a = base + (uint32_t)((cn * 32 + jp * 16 + rK) * LQ + d * 16 + cK) * 2;
                ldsm_x4(kh, a);
                ldsm_x4(kl, a + 64 * LQ * 2);
                mma16816(s[jp * 2],     qh[d], kh[0], kh[1]);
                mma16816(s[jp * 2],     ql[d], kh[0], kh[1]);
                mma16816(s[jp * 2],     qh[d], kl[0], kl[1]);
                mma16816(s[jp * 2 + 1], qh[d], kh[2], kh[3]);
                mma16816(s[jp * 2 + 1], ql[d], kh[2], kh[3]);
                mma16816(s[jp * 2 + 1], qh[d], kl[2], kl[3]);
            }
        }

        // ---- exp + row-sum ----------------------------------------------
        #pragma unroll
        for (int j = 0; j < 4; j++) {
            s[j][0] = __expf(s[j][0]); s[j][1] = __expf(s[j][1]);
            s[j][2] = __expf(s[j][2]); s[j][3] = __expf(s[j][3]);
            ls0 += s[j][0] + s[j][1];
            ls1 += s[j][2] + s[j][3];
        }

        // ---- repack P -> A fragments (register-only) ----------------------
        uint32_t ph[2][4], pl[2][4];
        #pragma unroll
        for (int kk = 0; kk < 2; kk++) {
            int j0 = kk * 2;
            split2(s[j0][0],     s[j0][1],     ph[kk][0], pl[kk][0]);
            split2(s[j0][2],     s[j0][3],     ph[kk][1], pl[kk][1]);
            split2(s[j0 + 1][0], s[j0 + 1][1], ph[kk][2], pl[kk][2]);
            split2(s[j0 + 1][2], s[j0 + 1][3], ph[kk][3], pl[kk][3]);
        }

        // ---- O_partial += P @ V (3-term) ----------------------------------
        #pragma unroll
        for (int kk = 0; kk < 2; kk++) {
            #pragma unroll
            for (int np = 0; np < 4; np++) {
                uint32_t vh[4], vl[4];
                uint32_t a = base + (uint32_t)(2 * 64 * LQ + (cn * 32 + kk * 16 + rA) * LQ + np * 16 + cA) * 2;
                ldsm_x4_t(vh, a);
                ldsm_x4_t(vl, a + 64 * LQ * 2);
                mma16816(oacc[np * 2],     ph[kk], vh[0], vh[1]);
                mma16816(oacc[np * 2],     pl[kk], vh[0], vh[1]);
                mma16816(oacc[np * 2],     ph[kk], vl[0], vl[1]);
                mma16816(oacc[np * 2 + 1], ph[kk], vh[2], vh[3]);
                mma16816(oacc[np * 2 + 1], pl[kk], vh[2], vh[3]);
                mma16816(oacc[np * 2 + 1], ph[kk], vl[2], vl[3]);
            }
        }
    }

    // ---- row-sum halves ----------------------------------------------------
    ls0 += __shfl_xor_sync(0xffffffffu, ls0, 1);
    ls0 += __shfl_xor_sync(0xffffffffu, ls0, 2);
    ls1 += __shfl_xor_sync(0xffffffffu, ls1, 1);
    ls1 += __shfl_xor_sync(0xffffffffu, ls1, 2);
    if ((lane & 3) == 0) {
        lbuf[cn][rm * 16 + (lane >> 2)]     = ls0;
        lbuf[cn][rm * 16 + (lane >> 2) + 8] = ls1;
    }

    __syncthreads();

    // ---- merge O partials through smem (aliased over KVs) -------------------
    float* obuf = (float*)KVs;
    {
        int r0 = rm * 16 + (lane >> 2);
        int c0 = (lane & 3) * 2;
        float* ob = obuf + cn * 64 * LSO;
        #pragma unroll
        for (int n = 0; n < 8; n++) {
            float2 lo; lo.x = oacc[n][0]; lo.y = oacc[n][1];
            float2 hi; hi.x = oacc[n][2]; hi.y = oacc[n][3];
            *(float2*)&ob[r0 * LSO + n * 8 + c0]       = lo;
            *(float2*)&ob[(r0 + 8) * LSO + n * 8 + c0] = hi;
        }
    }
    __syncthreads();

    // ---- normalize + split-write ctx hi/lo -----------------------------------
    {
        const float inv = 1.0f / (lbuf[0][row] + lbuf[1][row]);
        __nv_bfloat16* chp = Chg + gbase;
        __nv_bfloat16* clp = Clg + gbase;
        #pragma unroll
        for (int g = 0; g < 2; g++) {
            float v[8];
            #pragma unroll
            for (int e = 0; e < 8; e++) {
                int cc = cseg + g * 8 + e;
                v[e] = (obuf[row * LSO + cc] + obuf[64 * LSO + row * LSO + cc]) * inv;
            }
            uint4 hv, lv;
            split2(v[0], v[1], hv.x, lv.x);
            split2(v[2], v[3], hv.y, lv.y);
            split2(v[4], v[5], hv.z, lv.z);
            split2(v[6], v[7], hv.w, lv.w);
            *(uint4*)(chp + g * 8) = hv;
            *(uint4*)(clp + g * 8) = lv;
        }
    }
}

// ---------------------------------------------------------------------------
extern "C" void kernel_launch(void* const* d_in, const int* in_sizes, int n_in,
                              void* d_out, int out_size)
{
    const float* queries = (const float*)d_in[0];
    const float* keys    = (const float*)d_in[1];
    const float* values  = (const float*)d_in[2];
    const float* Wq      = (const float*)d_in[3];
    const float* Wk      = (const float*)d_in[4];
    const float* Wv      = (const float*)d_in[5];
    const float* Wo      = (const float*)d_in[6];
    float* out = (float*)d_out;

    __nv_bfloat16 *iqh,*iql,*ikh,*ikl,*ivh,*ivl;
    __nv_bfloat16 *wqh,*wql,*wkh,*wkl,*wvh,*wvl,*woh,*wol;
    __nv_bfloat16 *Qh,*Ql,*Kh,*Kl,*Vh,*Vl,*Ch,*Cl;
    cudaGetSymbolAddress((void**)&iqh, g_iqh); cudaGetSymbolAddress((void**)&iql, g_iql);
    cudaGetSymbolAddress((void**)&ikh, g_ikh); cudaGetSymbolAddress((void**)&ikl, g_ikl);
    cudaGetSymbolAddress((void**)&ivh, g_ivh); cudaGetSymbolAddress((void**)&ivl, g_ivl);
    cudaGetSymbolAddress((void**)&wqh, g_wqh); cudaGetSymbolAddress((void**)&wql, g_wql);
    cudaGetSymbolAddress((void**)&wkh, g_wkh); cudaGetSymbolAddress((void**)&wkl, g_wkl);
    cudaGetSymbolAddress((void**)&wvh, g_wvh); cudaGetSymbolAddress((void**)&wvl, g_wvl);
    cudaGetSymbolAddress((void**)&woh, g_woh); cudaGetSymbolAddress((void**)&wol, g_wol);
    cudaGetSymbolAddress((void**)&Qh, g_Qh); cudaGetSymbolAddress((void**)&Ql, g_Ql);
    cudaGetSymbolAddress((void**)&Kh, g_Kh); cudaGetSymbolAddress((void**)&Kl, g_Kl);
    cudaGetSymbolAddress((void**)&Vh, g_Vh); cudaGetSymbolAddress((void**)&Vl, g_Vl);
    cudaGetSymbolAddress((void**)&Ch, g_Ch); cudaGetSymbolAddress((void**)&Cl, g_Cl);

    cudaFuncSetAttribute(gemm_bf16, cudaFuncAttributeMaxDynamicSharedMemorySize, GEMM_SMEM);

    // ---- splits ----
    split_k<<<NELEM / 4 / 256, 256>>>(queries, iqh, iql, NELEM / 4);
    split_k<<<NELEM / 4 / 256, 256>>>(keys,    ikh, ikl, NELEM / 4);
    split_k<<<NELEM / 4 / 256, 256>>>(values,  ivh, ivl, NELEM / 4);
    split_k<<<WELEM / 4 / 256, 256>>>(Wq, wqh, wql, WELEM / 4);
    split_k<<<WELEM / 4 / 256, 256>>>(Wk, wkh, wkl, WELEM / 4);
    split_k<<<WELEM / 4 / 256, 256>>>(Wv, wvh, wvl, WELEM / 4);
    split_k<<<WELEM / 4 / 256, 256>>>(Wo, woh, wol, WELEM / 4);

    dim3 ggrid(DD / 128, MROWS / 128);  // (8, 32)
    const float qscale = 0.125f;        // HD^-0.5

    gemm_bf16<<<ggrid, 256, GEMM_SMEM>>>(iqh, iql, wqh, wql, nullptr, Qh, Ql, qscale, 1);
    gemm_bf16<<<ggrid, 256, GEMM_SMEM>>>(ikh, ikl, wkh, wkl, nullptr, Kh, Kl, 1.0f, 1);
    gemm_bf16<<<ggrid, 256, GEMM_SMEM>>>(ivh, ivl, wvh, wvl, nullptr, Vh, Vl, 1.0f, 1);

    attn_mma<<<dim3(SS / 64, HH, BB), 256>>>(Qh, Ql, Kh, Kl, Vh, Vl, Ch, Cl);

    gemm_bf16<<<ggrid, 256, GEMM_SMEM>>>(Ch, Cl, woh, wol, out, nullptr, nullptr, 1.0f, 0);
}